// round 5
// baseline (speedup 1.0000x reference)
#include <cuda_runtime.h>

// query [32, 2048] f32, W [2048, 100] f32, out [32, 100] f32.
// out[b,o] = sum_j (q[b,j] - (2048*trunc(q[b,j]) + S[b]))^2 * W[j,o]
// S[b] = sum_j trunc(q[b,j]).  Integer-exact in f32 (|values| < 2^24).

#define BATCH     32
#define NDIM      2048
#define NOUT      100
#define NTHREADS  1024
#define YSPLIT    4
#define COLS_PER_BLK 25          // NOUT / YSPLIT
#define NPARTS    32             // warps per block
#define JPART     (NDIM / NPARTS)  // 64

__global__ __launch_bounds__(NTHREADS)
void fused_rem_matvec(const float* __restrict__ q,
                      const float* __restrict__ W,
                      float* __restrict__ out) {
    const int b       = blockIdx.x;
    const int colbase = blockIdx.y * COLS_PER_BLK;

    __shared__ float rem[NDIM];              // 8 KB
    __shared__ int   wsum[NPARTS];
    __shared__ float partial[NPARTS][33];    // padded: conflict-free column reads

    const int tid  = threadIdx.x;
    const int lane = tid & 31;
    const int wrp  = tid >> 5;

    // ---- Phase 1: one global pass over q; c and q stay in registers ----
    const float2 v = ((const float2*)(q + b * NDIM))[tid];
    const int c0 = (int)v.x;                 // trunc toward zero == astype(int32)
    const int c1 = (int)v.y;

    int s = __reduce_add_sync(0xffffffffu, c0 + c1);
    if (lane == 0) wsum[wrp] = s;
    __syncthreads();

    int S = 0;
    #pragma unroll
    for (int w = 0; w < NPARTS; w++) S += wsum[w];
    const float Sf = (float)S;

    // ---- Phase 2: rem = (q - (2048*c + S))^2, straight from registers ----
    const float d0 = v.x - fmaf(2048.0f, (float)c0, Sf);
    const float d1 = v.y - fmaf(2048.0f, (float)c1, Sf);
    ((float2*)rem)[tid] = make_float2(d0 * d0, d1 * d1);
    __syncthreads();

    // ---- Phase 3: matvec. lane -> output col (coalesced W), warp -> j-part ----
    float acc = 0.0f;
    if (lane < COLS_PER_BLK) {
        const float* Wp = W + colbase + lane;
        const int j0 = wrp * JPART;
        #pragma unroll 16
        for (int j = j0; j < j0 + JPART; j++)
            acc = fmaf(rem[j], __ldg(&Wp[j * NOUT]), acc);
    }
    partial[wrp][lane] = acc;
    __syncthreads();

    // ---- Phase 4: warp w reduces output column w (25 warps in parallel) ----
    if (wrp < COLS_PER_BLK) {
        float r = partial[lane][wrp];        // stride-33 rows: conflict-free
        #pragma unroll
        for (int off = 16; off > 0; off >>= 1)
            r += __shfl_down_sync(0xffffffffu, r, off);
        if (lane == 0) out[b * NOUT + colbase + wrp] = r;
    }
}

extern "C" void kernel_launch(void* const* d_in, const int* in_sizes, int n_in,
                              void* d_out, int out_size) {
    const float* q = (const float*)d_in[0];   // [32, 2048]
    const float* W = (const float*)d_in[1];   // [2048, 100]
    float* out = (float*)d_out;               // [32, 100]
    (void)in_sizes; (void)n_in; (void)out_size;

    dim3 grid(BATCH, YSPLIT);
    fused_rem_matvec<<<grid, NTHREADS>>>(q, W, out);
}

// round 8
// speedup vs baseline: 1.7316x; 1.7316x over previous
#include <cuda_runtime.h>

// query [32, 2048] f32, W [2048, 100] f32, out [32, 100] f32.
// out[b,o] = sum_j (q[b,j] - (2048*trunc(q[b,j]) + S[b]))^2 * W[j,o]
// S[b] = sum_j trunc(q[b,j]).  Integer-exact in f32 (|values| < 2^24).

#define BATCH     32
#define NDIM      2048
#define NOUT      100
#define NTHREADS  512
#define YSPLIT    4
#define KSPLIT    4
#define COLS_PER_BLK (NOUT / YSPLIT)      // 25
#define KCHUNK    (NDIM / KSPLIT)         // 512
#define NWARPS    (NTHREADS / 32)         // 16
#define JPART     (KCHUNK / NWARPS)       // 32 j's per warp

__device__ int g_S[BATCH];                // per-batch sum of trunc(q)

// Kernel A: one block per batch. S[b] -> g_S, zero out[b,:].
__global__ __launch_bounds__(NTHREADS)
void prep_kernel(const float* __restrict__ q, float* __restrict__ out) {
    const int b   = blockIdx.x;
    const int tid = threadIdx.x;
    const int lane = tid & 31;
    const int wrp  = tid >> 5;

    __shared__ int wsum[NWARPS];

    const float4 v = ((const float4*)(q + b * NDIM))[tid];
    const int cs = (int)v.x + (int)v.y + (int)v.z + (int)v.w;

    const int s = __reduce_add_sync(0xffffffffu, cs);
    if (lane == 0) wsum[wrp] = s;
    __syncthreads();

    if (tid == 0) {
        int S = 0;
        #pragma unroll
        for (int w = 0; w < NWARPS; w++) S += wsum[w];
        g_S[b] = S;
    }
    if (tid < NOUT) out[b * NOUT + tid] = 0.0f;
}

// Kernel B: grid (32, YSPLIT, KSPLIT). Each block: 512-j chunk x 25 cols.
__global__ __launch_bounds__(NTHREADS)
void matvec_kernel(const float* __restrict__ q,
                   const float* __restrict__ W,
                   float* __restrict__ out) {
    const int b       = blockIdx.x;
    const int colbase = blockIdx.y * COLS_PER_BLK;
    const int kbase   = blockIdx.z * KCHUNK;

    __shared__ float rem[KCHUNK];               // 2 KB
    __shared__ float partial[NWARPS][33];       // padded

    const int tid  = threadIdx.x;
    const int lane = tid & 31;
    const int wrp  = tid >> 5;

    // rem for this K-chunk: one element per thread, straight to smem.
    const float v  = q[b * NDIM + kbase + tid];
    const float Sf = (float)g_S[b];
    const float d  = v - fmaf(2048.0f, (float)(int)v, Sf);
    rem[tid] = d * d;
    __syncthreads();

    // Matvec: warp -> 32-j slice, lane -> output col (coalesced W rows).
    float acc = 0.0f;
    if (lane < COLS_PER_BLK) {
        const float* Wp = W + colbase + lane;
        const int j0 = wrp * JPART;
        #pragma unroll
        for (int i = 0; i < JPART; i++)
            acc = fmaf(rem[j0 + i], __ldg(&Wp[(kbase + j0 + i) * NOUT]), acc);
    }
    partial[wrp][lane] = acc;
    __syncthreads();

    // Threads 0..24 fold the 16 warp partials for their column, atomic out.
    if (tid < COLS_PER_BLK) {
        float r = 0.0f;
        #pragma unroll
        for (int p = 0; p < NWARPS; p++) r += partial[p][tid];
        atomicAdd(&out[b * NOUT + colbase + tid], r);
    }
}

extern "C" void kernel_launch(void* const* d_in, const int* in_sizes, int n_in,
                              void* d_out, int out_size) {
    const float* q = (const float*)d_in[0];   // [32, 2048]
    const float* W = (const float*)d_in[1];   // [2048, 100]
    float* out = (float*)d_out;               // [32, 100]
    (void)in_sizes; (void)n_in; (void)out_size;

    prep_kernel<<<BATCH, NTHREADS>>>(q, out);
    dim3 grid(BATCH, YSPLIT, KSPLIT);
    matvec_kernel<<<grid, NTHREADS>>>(q, W, out);
}